// round 15
// baseline (speedup 1.0000x reference)
#include <cuda_runtime.h>
#include <math.h>

#define TLEN 8192
#define NTH  1024
#define EPT  8           // elements per thread in prep (NTH*EPT == TLEN)
#define NWARP (NTH/32)   // 32 warps

__device__ float4 g_k4[TLEN / 4];   // final kernel k (with 1/W folded in)

__device__ __forceinline__ float squashf(float v, float lo, float hi) {
    return lo + (hi - lo) / (1.0f + __expf(-v));
}

// ---------------------------------------------------------------------------
// Prep: compute k_t / W entirely in registers + warp shuffles.
// R15: exponentials computed INCREMENTALLY (both exp families are geometric
// in the element index -> 2 MUFU exps per thread instead of 17), divisions
// via __fdividef (single RCP). ~2.5x less MUFU work on the single prep SM.
// ---------------------------------------------------------------------------
__global__ void __launch_bounds__(NTH) prep_kernel(
    const float* fsn, const float* fin, const float* fdn, const float* ftn,
    const float* won, const float* wtn, const void* Fin)
{
    __shared__ float sWA[NWARP];
    __shared__ float sWB[NWARP];
    __shared__ float sEx[NTH];

    const int tid  = threadIdx.x;
    const int lane = tid & 31;
    const int wid  = tid >> 5;

    // F is an int scalar (44100); guard against float encoding.
    int   Fi = *(const int*)Fin;
    float Ff = *(const float*)Fin;
    float F  = (Fi > 0 && Fi < 100000000) ? (float)Fi : Ff;

    const float f_start = squashf(*fsn, 200.0f, 4000.0f);
    const float f_inf   = squashf(*fin, 20.0f, 500.0f);
    const float f_decay = squashf(*fdn, 0.0f, 2.0f);
    const float f_T     = squashf(*ftn, 0.0f, 2.0f);
    const float w_off   = squashf(*won, 0.0f, 1.0f);
    const float w_T     = squashf(*wtn, 0.01f, 0.5f);

    const float c      = 0.5098245285339035f * F * 0.3183098861837907f;
    const float lbase  = -0.35667494393873245f - f_decay * 2.302585092994046f;
    const float escale = 0.1f * __expf(f_T * 2.302585092994046f);
    const float inv_wT = 1.0f / w_T;
    const float lk     = lbase * escale * (1.0f / (float)TLEN);

    const float dF   = f_start - f_inf;
    const float rE   = __expf(-lk);              // per-element ratio for f-exp
    const float rW   = __expf(inv_wT * (1.0f / (float)TLEN)); // ratio for w-exp

    float atau[EPT + 1];
    float wreg[EPT];
    const int tbase = TLEN - 1 - tid * EPT;   // t(0)

    // f-exp at tau(0) = tbase+1, advancing by rE each step (tau decreases).
    {
        float e = __expf(lk * (float)(tbase + 1));
        #pragma unroll
        for (int j = 0; j <= EPT; j++) {
            float f = fmaf(dF, e, f_inf);
            atau[j] = __fdividef(f - c, f + c);
            e *= rE;
        }
    }
    // w: sigmoid((t - w_off)/w_T) = 1/(1 + q), q = exp((w_off - t)*inv_wT),
    // q advances by rW each step (t decreases).
    float wsum = 0.0f;
    {
        float q = __expf((w_off - (float)tbase * (1.0f / (float)TLEN)) * inv_wT);
        #pragma unroll
        for (int j = 0; j < EPT; j++) {
            wreg[j] = __fdividef(1.0f, 1.0f + q);
            wsum += wreg[j];
            q *= rW;
        }
    }

    const bool first = (tid == 0);             // owns s=0   (t=8191)
    const bool last  = (tid == NTH - 1);       // owns s=8191 (t=0)

    float lreg[EPT];   // lambda2 after scan1, overwritten by lambda1

    // ===================== scan 1 : lambda2 ==============================
    {
        float A = 1.0f, B = 0.0f;
        #pragma unroll
        for (int j = 0; j < EPT; j++) {
            float Ae = (first && j == 0) ? 0.0f : -atau[j];
            float Be = (last  && j == EPT - 1) ? 0.0f : wreg[j];
            B = fmaf(Ae, B, Be);
            A = Ae * A;
        }
        #pragma unroll
        for (int d = 1; d < 32; d <<= 1) {
            float pA = __shfl_up_sync(0xffffffffu, A, d);
            float pB = __shfl_up_sync(0xffffffffu, B, d);
            if (lane >= d) { B = fmaf(A, pB, B); A = A * pA; }
        }
        if (lane == 31) { sWA[wid] = A; sWB[wid] = B; }
        __syncthreads();
        if (wid == 0) {
            float a = sWA[lane], b = sWB[lane];
            #pragma unroll
            for (int d = 1; d < 32; d <<= 1) {
                float pA = __shfl_up_sync(0xffffffffu, a, d);
                float pB = __shfl_up_sync(0xffffffffu, b, d);
                if (lane >= d) { b = fmaf(a, pB, b); a = a * pA; }
            }
            sWA[lane] = a; sWB[lane] = b;
        }
        __syncthreads();
        float eA = __shfl_up_sync(0xffffffffu, A, 1);
        float eB = __shfl_up_sync(0xffffffffu, B, 1);
        if (lane == 0) { eA = 1.0f; eB = 0.0f; }
        float h = (wid > 0) ? fmaf(eA, sWB[wid - 1], eB) : eB;
        #pragma unroll
        for (int j = 0; j < EPT; j++) {
            float Ae = (first && j == 0) ? 0.0f : -atau[j];
            float Be = (last  && j == EPT - 1) ? 0.0f : wreg[j];
            h = fmaf(Ae, h, Be);
            lreg[j] = h;
        }
    }

    sEx[tid] = lreg[EPT - 1];
    __syncthreads();
    float prevL2 = (tid > 0) ? sEx[tid - 1] : 0.0f;
    __syncthreads();

    // ===================== scan 2 : lambda1 ==============================
    float l2_last = lreg[EPT - 1];
    {
        float A = 1.0f, B = 0.0f;
        #pragma unroll
        for (int j = 0; j < EPT; j++) {
            float bt  = 0.5f * (atau[j + 1] + 1.0f);
            float bt1 = 0.5f * (atau[j] + 1.0f);
            float l2c = lreg[j];
            float l2p = (j == 0) ? prevL2 : lreg[j - 1];
            float Be;
            if (first && j == 0)            Be = bt * l2c;
            else if (last && j == EPT - 1)  Be = bt1 * l2p;
            else                            Be = fmaf(bt, l2c, bt1 * l2p);
            float Ae = (first && j == 0) ? 0.0f : -atau[j];
            B = fmaf(Ae, B, Be);
            A = Ae * A;
        }
        #pragma unroll
        for (int d = 1; d < 32; d <<= 1) {
            float pA = __shfl_up_sync(0xffffffffu, A, d);
            float pB = __shfl_up_sync(0xffffffffu, B, d);
            if (lane >= d) { B = fmaf(A, pB, B); A = A * pA; }
        }
        if (lane == 31) { sWA[wid] = A; sWB[wid] = B; }
        __syncthreads();
        if (wid == 0) {
            float a = sWA[lane], b = sWB[lane];
            #pragma unroll
            for (int d = 1; d < 32; d <<= 1) {
                float pA = __shfl_up_sync(0xffffffffu, a, d);
                float pB = __shfl_up_sync(0xffffffffu, b, d);
                if (lane >= d) { b = fmaf(a, pB, b); a = a * pA; }
            }
            sWA[lane] = a; sWB[lane] = b;
        }
        __syncthreads();
        float eA = __shfl_up_sync(0xffffffffu, A, 1);
        float eB = __shfl_up_sync(0xffffffffu, B, 1);
        if (lane == 0) { eA = 1.0f; eB = 0.0f; }
        float h = (wid > 0) ? fmaf(eA, sWB[wid - 1], eB) : eB;
        float l2p = prevL2;
        #pragma unroll
        for (int j = 0; j < EPT; j++) {
            float bt  = 0.5f * (atau[j + 1] + 1.0f);
            float bt1 = 0.5f * (atau[j] + 1.0f);
            float l2c = lreg[j];
            float Be;
            if (first && j == 0)            Be = bt * l2c;
            else if (last && j == EPT - 1)  Be = bt1 * l2p;
            else                            Be = fmaf(bt, l2c, bt1 * l2p);
            float Ae = (first && j == 0) ? 0.0f : -atau[j];
            h = fmaf(Ae, h, Be);
            lreg[j] = h;                    // l1
            l2p = l2c;
        }
    }

    __syncthreads();
    sEx[tid] = lreg[EPT - 1];
    __syncthreads();
    float prevL1 = (tid > 0) ? sEx[tid - 1] : 0.0f;

    // ===================== W = sum(w) ====================================
    #pragma unroll
    for (int d = 16; d > 0; d >>= 1)
        wsum += __shfl_down_sync(0xffffffffu, wsum, d);
    __syncthreads();
    if (lane == 0) sWA[wid] = wsum;
    __syncthreads();
    if (tid == 0) {
        float s = 0.0f;
        #pragma unroll
        for (int i = 0; i < NWARP; i++) s += sWA[i];
        sWB[0] = 1.0f / s;
    }
    __syncthreads();
    const float invW = sWB[0];

    // ===================== emit k ========================================
    float* kf = (float*)g_k4;
    #pragma unroll
    for (int j = 0; j < EPT; j++) {
        float bt  = 0.5f * (atau[j + 1] + 1.0f);
        float bt1 = 0.5f * (atau[j] + 1.0f);
        float l1c = lreg[j];
        float l1p = (j == 0) ? prevL1 : lreg[j - 1];
        float kv;
        if (first && j == 0) {
            kv = bt * l1c;
        } else if (last && j == EPT - 1) {
            kv = wreg[EPT - 1] + fmaf(bt1, lreg[EPT - 2], l1c + l2_last);
        } else {
            kv = fmaf(bt, l1c, bt1 * l1p);
        }
        kf[tbase - j] = kv * invW;
    }
}

// ---------------------------------------------------------------------------
// GEMV: one row per CTA, 256 threads, 8+8 batched float4 register-LDG loads.
// (R13 shape, fast-bucket member; byte-identical to R13.)
// ---------------------------------------------------------------------------
__global__ void __launch_bounds__(256) gemv_kernel(
    const float* __restrict__ X, float* __restrict__ out)
{
    const int row = blockIdx.x;
    const int tid = threadIdx.x;
    const float4* __restrict__ xr = (const float4*)(X + (size_t)row * TLEN);

    float4 x[8];
    float4 k[8];
    #pragma unroll
    for (int i = 0; i < 8; i++)
        x[i] = xr[i * 256 + tid];
    #pragma unroll
    for (int i = 0; i < 8; i++)
        k[i] = g_k4[i * 256 + tid];

    float a0 = 0.0f, a1 = 0.0f, a2 = 0.0f, a3 = 0.0f;
    #pragma unroll
    for (int i = 0; i < 8; i++) {
        a0 = fmaf(x[i].x, k[i].x, a0);
        a1 = fmaf(x[i].y, k[i].y, a1);
        a2 = fmaf(x[i].z, k[i].z, a2);
        a3 = fmaf(x[i].w, k[i].w, a3);
    }
    float acc = (a0 + a1) + (a2 + a3);

    // warp reduce
    #pragma unroll
    for (int off = 16; off > 0; off >>= 1)
        acc += __shfl_down_sync(0xffffffffu, acc, off);

    __shared__ float sred[8];
    int w = tid >> 5, l = tid & 31;
    if (l == 0) sred[w] = acc;
    __syncthreads();
    if (tid == 0) {
        float s = 0.0f;
        #pragma unroll
        for (int i = 0; i < 8; i++) s += sred[i];
        out[row] = s;
    }
}

extern "C" void kernel_launch(void* const* d_in, const int* in_sizes, int n_in,
                              void* d_out, int out_size)
{
    const float* X = (const float*)d_in[0];
    const void*  F = d_in[1];

    prep_kernel<<<1, NTH>>>(
        (const float*)d_in[2], (const float*)d_in[3], (const float*)d_in[4],
        (const float*)d_in[5], (const float*)d_in[6], (const float*)d_in[7], F);

    int rows = in_sizes[0] / TLEN;
    gemv_kernel<<<rows, 256>>>(X, (float*)d_out);
}

// round 16
// speedup vs baseline: 1.1347x; 1.1347x over previous
#include <cuda_runtime.h>
#include <math.h>

#define TLEN 8192
#define NTH  1024
#define EPT  8           // elements per thread (NTH*EPT == TLEN)
#define NWARP (NTH/32)   // 32 warps

__device__ __forceinline__ float squashf(float v, float lo, float hi) {
    return lo + (hi - lo) / (1.0f + __expf(-v));
}

// ---------------------------------------------------------------------------
// Fused persistent kernel: each CTA computes the adjoint-scan kernel k ONCE
// (k values stay in registers, mapped to the same t-positions as this
// thread's x loads), then streams its assigned rows with double-buffered
// register LDGs. No second launch, no k memory traffic at all.
// ---------------------------------------------------------------------------
__global__ void __launch_bounds__(NTH) fused_kernel(
    const float* __restrict__ X, float* __restrict__ out, int rows,
    const float* fsn, const float* fin, const float* fdn, const float* ftn,
    const float* won, const float* wtn, const void* Fin)
{
    __shared__ float sWA[NWARP];
    __shared__ float sWB[NWARP];
    __shared__ float sEx[NTH];

    const int tid  = threadIdx.x;
    const int lane = tid & 31;
    const int wid  = tid >> 5;

    // ---- issue FIRST row's X loads immediately (hidden under prep) -------
    // Thread tid owns t in [8*(1023-tid), 8*(1023-tid)+8) -> 2 float4s.
    const int fi = 2 * (NTH - 1 - tid);
    int row = blockIdx.x;
    float4 xa, xb;
    if (row < rows) {
        const float4* xr = (const float4*)(X + (size_t)row * TLEN);
        xa = xr[fi]; xb = xr[fi + 1];
    }

    // ===================== prep: coefficients =============================
    int   Fi = *(const int*)Fin;
    float Ff = *(const float*)Fin;
    float F  = (Fi > 0 && Fi < 100000000) ? (float)Fi : Ff;

    const float f_start = squashf(*fsn, 200.0f, 4000.0f);
    const float f_inf   = squashf(*fin, 20.0f, 500.0f);
    const float f_decay = squashf(*fdn, 0.0f, 2.0f);
    const float f_T     = squashf(*ftn, 0.0f, 2.0f);
    const float w_off   = squashf(*won, 0.0f, 1.0f);
    const float w_T     = squashf(*wtn, 0.01f, 0.5f);

    const float c      = 0.5098245285339035f * F * 0.3183098861837907f;
    const float lbase  = -0.35667494393873245f - f_decay * 2.302585092994046f;
    const float escale = 0.1f * __expf(f_T * 2.302585092994046f);
    const float inv_wT = 1.0f / w_T;
    const float lk     = lbase * escale * (1.0f / (float)TLEN);

    const float dF = f_start - f_inf;
    const float rE = __expf(-lk);                              // f-exp ratio
    const float rW = __expf(inv_wT * (1.0f / (float)TLEN));    // w-exp ratio

    float atau[EPT + 1];
    float wreg[EPT];
    const int tbase = TLEN - 1 - tid * EPT;   // t(0)

    {
        float e = __expf(lk * (float)(tbase + 1));
        #pragma unroll
        for (int j = 0; j <= EPT; j++) {
            float f = fmaf(dF, e, f_inf);
            atau[j] = __fdividef(f - c, f + c);
            e *= rE;
        }
    }
    float wsum = 0.0f;
    {
        float q = __expf((w_off - (float)tbase * (1.0f / (float)TLEN)) * inv_wT);
        #pragma unroll
        for (int j = 0; j < EPT; j++) {
            wreg[j] = __fdividef(1.0f, 1.0f + q);
            wsum += wreg[j];
            q *= rW;
        }
    }

    const bool first = (tid == 0);
    const bool last  = (tid == NTH - 1);

    float lreg[EPT];

    // ===================== scan 1 : lambda2 ==============================
    {
        float A = 1.0f, B = 0.0f;
        #pragma unroll
        for (int j = 0; j < EPT; j++) {
            float Ae = (first && j == 0) ? 0.0f : -atau[j];
            float Be = (last  && j == EPT - 1) ? 0.0f : wreg[j];
            B = fmaf(Ae, B, Be);
            A = Ae * A;
        }
        #pragma unroll
        for (int d = 1; d < 32; d <<= 1) {
            float pA = __shfl_up_sync(0xffffffffu, A, d);
            float pB = __shfl_up_sync(0xffffffffu, B, d);
            if (lane >= d) { B = fmaf(A, pB, B); A = A * pA; }
        }
        if (lane == 31) { sWA[wid] = A; sWB[wid] = B; }
        __syncthreads();
        if (wid == 0) {
            float a = sWA[lane], b = sWB[lane];
            #pragma unroll
            for (int d = 1; d < 32; d <<= 1) {
                float pA = __shfl_up_sync(0xffffffffu, a, d);
                float pB = __shfl_up_sync(0xffffffffu, b, d);
                if (lane >= d) { b = fmaf(a, pB, b); a = a * pA; }
            }
            sWA[lane] = a; sWB[lane] = b;
        }
        __syncthreads();
        float eA = __shfl_up_sync(0xffffffffu, A, 1);
        float eB = __shfl_up_sync(0xffffffffu, B, 1);
        if (lane == 0) { eA = 1.0f; eB = 0.0f; }
        float h = (wid > 0) ? fmaf(eA, sWB[wid - 1], eB) : eB;
        #pragma unroll
        for (int j = 0; j < EPT; j++) {
            float Ae = (first && j == 0) ? 0.0f : -atau[j];
            float Be = (last  && j == EPT - 1) ? 0.0f : wreg[j];
            h = fmaf(Ae, h, Be);
            lreg[j] = h;
        }
    }

    sEx[tid] = lreg[EPT - 1];
    __syncthreads();
    float prevL2 = (tid > 0) ? sEx[tid - 1] : 0.0f;
    __syncthreads();

    // ===================== scan 2 : lambda1 ==============================
    float l2_last = lreg[EPT - 1];
    {
        float A = 1.0f, B = 0.0f;
        #pragma unroll
        for (int j = 0; j < EPT; j++) {
            float bt  = 0.5f * (atau[j + 1] + 1.0f);
            float bt1 = 0.5f * (atau[j] + 1.0f);
            float l2c = lreg[j];
            float l2p = (j == 0) ? prevL2 : lreg[j - 1];
            float Be;
            if (first && j == 0)            Be = bt * l2c;
            else if (last && j == EPT - 1)  Be = bt1 * l2p;
            else                            Be = fmaf(bt, l2c, bt1 * l2p);
            float Ae = (first && j == 0) ? 0.0f : -atau[j];
            B = fmaf(Ae, B, Be);
            A = Ae * A;
        }
        #pragma unroll
        for (int d = 1; d < 32; d <<= 1) {
            float pA = __shfl_up_sync(0xffffffffu, A, d);
            float pB = __shfl_up_sync(0xffffffffu, B, d);
            if (lane >= d) { B = fmaf(A, pB, B); A = A * pA; }
        }
        if (lane == 31) { sWA[wid] = A; sWB[wid] = B; }
        __syncthreads();
        if (wid == 0) {
            float a = sWA[lane], b = sWB[lane];
            #pragma unroll
            for (int d = 1; d < 32; d <<= 1) {
                float pA = __shfl_up_sync(0xffffffffu, a, d);
                float pB = __shfl_up_sync(0xffffffffu, b, d);
                if (lane >= d) { b = fmaf(a, pB, b); a = a * pA; }
            }
            sWA[lane] = a; sWB[lane] = b;
        }
        __syncthreads();
        float eA = __shfl_up_sync(0xffffffffu, A, 1);
        float eB = __shfl_up_sync(0xffffffffu, B, 1);
        if (lane == 0) { eA = 1.0f; eB = 0.0f; }
        float h = (wid > 0) ? fmaf(eA, sWB[wid - 1], eB) : eB;
        float l2p = prevL2;
        #pragma unroll
        for (int j = 0; j < EPT; j++) {
            float bt  = 0.5f * (atau[j + 1] + 1.0f);
            float bt1 = 0.5f * (atau[j] + 1.0f);
            float l2c = lreg[j];
            float Be;
            if (first && j == 0)            Be = bt * l2c;
            else if (last && j == EPT - 1)  Be = bt1 * l2p;
            else                            Be = fmaf(bt, l2c, bt1 * l2p);
            float Ae = (first && j == 0) ? 0.0f : -atau[j];
            h = fmaf(Ae, h, Be);
            lreg[j] = h;                    // l1
            l2p = l2c;
        }
    }

    __syncthreads();
    sEx[tid] = lreg[EPT - 1];
    __syncthreads();
    float prevL1 = (tid > 0) ? sEx[tid - 1] : 0.0f;

    // ===================== W = sum(w) ====================================
    #pragma unroll
    for (int d = 16; d > 0; d >>= 1)
        wsum += __shfl_down_sync(0xffffffffu, wsum, d);
    __syncthreads();
    if (lane == 0) sWA[wid] = wsum;
    __syncthreads();
    if (tid == 0) {
        float s = 0.0f;
        #pragma unroll
        for (int i = 0; i < NWARP; i++) s += sWA[i];
        sWB[0] = 1.0f / s;
    }
    __syncthreads();
    const float invW = sWB[0];

    // ===================== k stays in registers ==========================
    // x element f (0..7 within this thread's 8 floats) pairs with j = 7-f.
    float kk[EPT];
    #pragma unroll
    for (int j = 0; j < EPT; j++) {
        float bt  = 0.5f * (atau[j + 1] + 1.0f);
        float bt1 = 0.5f * (atau[j] + 1.0f);
        float l1c = lreg[j];
        float l1p = (j == 0) ? prevL1 : lreg[j - 1];
        float kv;
        if (first && j == 0) {
            kv = bt * l1c;
        } else if (last && j == EPT - 1) {
            kv = wreg[EPT - 1] + fmaf(bt1, lreg[EPT - 2], l1c + l2_last);
        } else {
            kv = fmaf(bt, l1c, bt1 * l1p);
        }
        kk[EPT - 1 - j] = kv * invW;
    }

    // ===================== persistent row loop ===========================
    while (row < rows) {
        int nrow = row + gridDim.x;
        float4 na, nb;
        if (nrow < rows) {                       // prefetch next row
            const float4* xr2 = (const float4*)(X + (size_t)nrow * TLEN);
            na = xr2[fi]; nb = xr2[fi + 1];
        }

        float a0, a1, a2, a3;
        a0 = xa.x * kk[0];          a1 = xa.y * kk[1];
        a2 = xa.z * kk[2];          a3 = xa.w * kk[3];
        a0 = fmaf(xb.x, kk[4], a0); a1 = fmaf(xb.y, kk[5], a1);
        a2 = fmaf(xb.z, kk[6], a2); a3 = fmaf(xb.w, kk[7], a3);
        float acc = (a0 + a1) + (a2 + a3);

        #pragma unroll
        for (int off = 16; off > 0; off >>= 1)
            acc += __shfl_down_sync(0xffffffffu, acc, off);
        if (lane == 0) sWA[wid] = acc;
        __syncthreads();
        if (wid == 0) {
            float v = sWA[lane];
            #pragma unroll
            for (int off = 16; off > 0; off >>= 1)
                v += __shfl_down_sync(0xffffffffu, v, off);
            if (lane == 0) out[row] = v;
        }
        __syncthreads();                          // sWA reuse guard

        xa = na; xb = nb;
        row = nrow;
    }
}

extern "C" void kernel_launch(void* const* d_in, const int* in_sizes, int n_in,
                              void* d_out, int out_size)
{
    const float* X = (const float*)d_in[0];
    const void*  F = d_in[1];
    int rows = in_sizes[0] / TLEN;

    int grid = 152;                 // GB300: 152 SMs, 1 CTA/SM persistent
    if (grid > rows) grid = rows;

    fused_kernel<<<grid, NTH>>>(
        X, (float*)d_out, rows,
        (const float*)d_in[2], (const float*)d_in[3], (const float*)d_in[4],
        (const float*)d_in[5], (const float*)d_in[6], (const float*)d_in[7], F);
}

// round 17
// speedup vs baseline: 1.1369x; 1.0019x over previous
#include <cuda_runtime.h>
#include <math.h>

#define TLEN 8192
#define NTH  1024
#define EPT  8           // elements per thread (NTH*EPT == TLEN)
#define NWARP (NTH/32)   // 32 warps

__device__ __forceinline__ float squashf(float v, float lo, float hi) {
    return lo + (hi - lo) / (1.0f + __expf(-v));
}

// ---------------------------------------------------------------------------
// Fused persistent kernel (R16 WIN + R17 row-pair pipeline):
// each CTA computes the adjoint-scan kernel k ONCE (k in registers, aligned
// with this thread's x positions), then streams row PAIRS with prefetch of
// the next pair and a single barrier per pair (ping-pong reduce buffers).
// ---------------------------------------------------------------------------
__global__ void __launch_bounds__(NTH) fused_kernel(
    const float* __restrict__ X, float* __restrict__ out, int rows,
    const float* fsn, const float* fin, const float* fdn, const float* ftn,
    const float* won, const float* wtn, const void* Fin)
{
    __shared__ float sWA[NWARP];
    __shared__ float sWB[NWARP];
    __shared__ float sEx[NTH];
    __shared__ float sR0[2][NWARP];
    __shared__ float sR1[2][NWARP];

    const int tid  = threadIdx.x;
    const int lane = tid & 31;
    const int wid  = tid >> 5;

    // Thread tid owns t in [8*(1023-tid), 8*(1023-tid)+8) -> 2 float4s.
    const int fi = 2 * (NTH - 1 - tid);
    const int npairs = rows >> 1;

    // ---- issue FIRST pair's X loads immediately (hidden under prep) ------
    int pi = blockIdx.x;
    float4 xa0, xb0, xa1, xb1;
    if (pi < npairs) {
        const float4* r0 = (const float4*)(X + (size_t)(2 * pi)     * TLEN);
        const float4* r1 = (const float4*)(X + (size_t)(2 * pi + 1) * TLEN);
        xa0 = r0[fi]; xb0 = r0[fi + 1];
        xa1 = r1[fi]; xb1 = r1[fi + 1];
    }

    // ===================== prep: coefficients =============================
    int   Fi = *(const int*)Fin;
    float Ff = *(const float*)Fin;
    float F  = (Fi > 0 && Fi < 100000000) ? (float)Fi : Ff;

    const float f_start = squashf(*fsn, 200.0f, 4000.0f);
    const float f_inf   = squashf(*fin, 20.0f, 500.0f);
    const float f_decay = squashf(*fdn, 0.0f, 2.0f);
    const float f_T     = squashf(*ftn, 0.0f, 2.0f);
    const float w_off   = squashf(*won, 0.0f, 1.0f);
    const float w_T     = squashf(*wtn, 0.01f, 0.5f);

    const float c      = 0.5098245285339035f * F * 0.3183098861837907f;
    const float lbase  = -0.35667494393873245f - f_decay * 2.302585092994046f;
    const float escale = 0.1f * __expf(f_T * 2.302585092994046f);
    const float inv_wT = 1.0f / w_T;
    const float lk     = lbase * escale * (1.0f / (float)TLEN);

    const float dF = f_start - f_inf;
    const float rE = __expf(-lk);
    const float rW = __expf(inv_wT * (1.0f / (float)TLEN));

    float atau[EPT + 1];
    float wreg[EPT];
    const int tbase = TLEN - 1 - tid * EPT;   // t(0)

    {
        float e = __expf(lk * (float)(tbase + 1));
        #pragma unroll
        for (int j = 0; j <= EPT; j++) {
            float f = fmaf(dF, e, f_inf);
            atau[j] = __fdividef(f - c, f + c);
            e *= rE;
        }
    }
    float wsum = 0.0f;
    {
        float q = __expf((w_off - (float)tbase * (1.0f / (float)TLEN)) * inv_wT);
        #pragma unroll
        for (int j = 0; j < EPT; j++) {
            wreg[j] = __fdividef(1.0f, 1.0f + q);
            wsum += wreg[j];
            q *= rW;
        }
    }

    const bool first = (tid == 0);
    const bool last  = (tid == NTH - 1);

    float lreg[EPT];

    // ===================== scan 1 : lambda2 ==============================
    {
        float A = 1.0f, B = 0.0f;
        #pragma unroll
        for (int j = 0; j < EPT; j++) {
            float Ae = (first && j == 0) ? 0.0f : -atau[j];
            float Be = (last  && j == EPT - 1) ? 0.0f : wreg[j];
            B = fmaf(Ae, B, Be);
            A = Ae * A;
        }
        #pragma unroll
        for (int d = 1; d < 32; d <<= 1) {
            float pA = __shfl_up_sync(0xffffffffu, A, d);
            float pB = __shfl_up_sync(0xffffffffu, B, d);
            if (lane >= d) { B = fmaf(A, pB, B); A = A * pA; }
        }
        if (lane == 31) { sWA[wid] = A; sWB[wid] = B; }
        __syncthreads();
        if (wid == 0) {
            float a = sWA[lane], b = sWB[lane];
            #pragma unroll
            for (int d = 1; d < 32; d <<= 1) {
                float pA = __shfl_up_sync(0xffffffffu, a, d);
                float pB = __shfl_up_sync(0xffffffffu, b, d);
                if (lane >= d) { b = fmaf(a, pB, b); a = a * pA; }
            }
            sWA[lane] = a; sWB[lane] = b;
        }
        __syncthreads();
        float eA = __shfl_up_sync(0xffffffffu, A, 1);
        float eB = __shfl_up_sync(0xffffffffu, B, 1);
        if (lane == 0) { eA = 1.0f; eB = 0.0f; }
        float h = (wid > 0) ? fmaf(eA, sWB[wid - 1], eB) : eB;
        #pragma unroll
        for (int j = 0; j < EPT; j++) {
            float Ae = (first && j == 0) ? 0.0f : -atau[j];
            float Be = (last  && j == EPT - 1) ? 0.0f : wreg[j];
            h = fmaf(Ae, h, Be);
            lreg[j] = h;
        }
    }

    sEx[tid] = lreg[EPT - 1];
    __syncthreads();
    float prevL2 = (tid > 0) ? sEx[tid - 1] : 0.0f;
    __syncthreads();

    // ===================== scan 2 : lambda1 ==============================
    float l2_last = lreg[EPT - 1];
    {
        float A = 1.0f, B = 0.0f;
        #pragma unroll
        for (int j = 0; j < EPT; j++) {
            float bt  = 0.5f * (atau[j + 1] + 1.0f);
            float bt1 = 0.5f * (atau[j] + 1.0f);
            float l2c = lreg[j];
            float l2p = (j == 0) ? prevL2 : lreg[j - 1];
            float Be;
            if (first && j == 0)            Be = bt * l2c;
            else if (last && j == EPT - 1)  Be = bt1 * l2p;
            else                            Be = fmaf(bt, l2c, bt1 * l2p);
            float Ae = (first && j == 0) ? 0.0f : -atau[j];
            B = fmaf(Ae, B, Be);
            A = Ae * A;
        }
        #pragma unroll
        for (int d = 1; d < 32; d <<= 1) {
            float pA = __shfl_up_sync(0xffffffffu, A, d);
            float pB = __shfl_up_sync(0xffffffffu, B, d);
            if (lane >= d) { B = fmaf(A, pB, B); A = A * pA; }
        }
        if (lane == 31) { sWA[wid] = A; sWB[wid] = B; }
        __syncthreads();
        if (wid == 0) {
            float a = sWA[lane], b = sWB[lane];
            #pragma unroll
            for (int d = 1; d < 32; d <<= 1) {
                float pA = __shfl_up_sync(0xffffffffu, a, d);
                float pB = __shfl_up_sync(0xffffffffu, b, d);
                if (lane >= d) { b = fmaf(a, pB, b); a = a * pA; }
            }
            sWA[lane] = a; sWB[lane] = b;
        }
        __syncthreads();
        float eA = __shfl_up_sync(0xffffffffu, A, 1);
        float eB = __shfl_up_sync(0xffffffffu, B, 1);
        if (lane == 0) { eA = 1.0f; eB = 0.0f; }
        float h = (wid > 0) ? fmaf(eA, sWB[wid - 1], eB) : eB;
        float l2p = prevL2;
        #pragma unroll
        for (int j = 0; j < EPT; j++) {
            float bt  = 0.5f * (atau[j + 1] + 1.0f);
            float bt1 = 0.5f * (atau[j] + 1.0f);
            float l2c = lreg[j];
            float Be;
            if (first && j == 0)            Be = bt * l2c;
            else if (last && j == EPT - 1)  Be = bt1 * l2p;
            else                            Be = fmaf(bt, l2c, bt1 * l2p);
            float Ae = (first && j == 0) ? 0.0f : -atau[j];
            h = fmaf(Ae, h, Be);
            lreg[j] = h;                    // l1
            l2p = l2c;
        }
    }

    __syncthreads();
    sEx[tid] = lreg[EPT - 1];
    __syncthreads();
    float prevL1 = (tid > 0) ? sEx[tid - 1] : 0.0f;

    // ===================== W = sum(w) ====================================
    #pragma unroll
    for (int d = 16; d > 0; d >>= 1)
        wsum += __shfl_down_sync(0xffffffffu, wsum, d);
    __syncthreads();
    if (lane == 0) sWA[wid] = wsum;
    __syncthreads();
    if (tid == 0) {
        float s = 0.0f;
        #pragma unroll
        for (int i = 0; i < NWARP; i++) s += sWA[i];
        sWB[0] = 1.0f / s;
    }
    __syncthreads();
    const float invW = sWB[0];

    // ===================== k stays in registers ==========================
    // x element f (0..7 within this thread's 8 floats) pairs with j = 7-f.
    float kk[EPT];
    #pragma unroll
    for (int j = 0; j < EPT; j++) {
        float bt  = 0.5f * (atau[j + 1] + 1.0f);
        float bt1 = 0.5f * (atau[j] + 1.0f);
        float l1c = lreg[j];
        float l1p = (j == 0) ? prevL1 : lreg[j - 1];
        float kv;
        if (first && j == 0) {
            kv = bt * l1c;
        } else if (last && j == EPT - 1) {
            kv = wreg[EPT - 1] + fmaf(bt1, lreg[EPT - 2], l1c + l2_last);
        } else {
            kv = fmaf(bt, l1c, bt1 * l1p);
        }
        kk[EPT - 1 - j] = kv * invW;
    }

    // ===================== persistent row-pair loop ======================
    int p = 0;
    while (pi < npairs) {
        int npi = pi + gridDim.x;
        float4 na0, nb0, na1, nb1;
        if (npi < npairs) {                      // prefetch next pair
            const float4* r0 = (const float4*)(X + (size_t)(2 * npi)     * TLEN);
            const float4* r1 = (const float4*)(X + (size_t)(2 * npi + 1) * TLEN);
            na0 = r0[fi]; nb0 = r0[fi + 1];
            na1 = r1[fi]; nb1 = r1[fi + 1];
        }

        // dot both rows with register k
        float a0, a1, b0, b1;
        a0 = xa0.x * kk[0];           a1 = xa0.y * kk[1];
        a0 = fmaf(xa0.z, kk[2], a0);  a1 = fmaf(xa0.w, kk[3], a1);
        a0 = fmaf(xb0.x, kk[4], a0);  a1 = fmaf(xb0.y, kk[5], a1);
        a0 = fmaf(xb0.z, kk[6], a0);  a1 = fmaf(xb0.w, kk[7], a1);
        b0 = xa1.x * kk[0];           b1 = xa1.y * kk[1];
        b0 = fmaf(xa1.z, kk[2], b0);  b1 = fmaf(xa1.w, kk[3], b1);
        b0 = fmaf(xb1.x, kk[4], b0);  b1 = fmaf(xb1.y, kk[5], b1);
        b0 = fmaf(xb1.z, kk[6], b0);  b1 = fmaf(xb1.w, kk[7], b1);
        float acc0 = a0 + a1;
        float acc1 = b0 + b1;

        // warp reduce both rows (ILP)
        #pragma unroll
        for (int off = 16; off > 0; off >>= 1) {
            acc0 += __shfl_down_sync(0xffffffffu, acc0, off);
            acc1 += __shfl_down_sync(0xffffffffu, acc1, off);
        }
        if (lane == 0) { sR0[p][wid] = acc0; sR1[p][wid] = acc1; }
        __syncthreads();
        if (wid == 0) {
            float v = sR0[p][lane];
            #pragma unroll
            for (int off = 16; off > 0; off >>= 1)
                v += __shfl_down_sync(0xffffffffu, v, off);
            if (lane == 0) out[2 * pi] = v;
        } else if (wid == 1) {
            float v = sR1[p][lane];
            #pragma unroll
            for (int off = 16; off > 0; off >>= 1)
                v += __shfl_down_sync(0xffffffffu, v, off);
            if (lane == 0) out[2 * pi + 1] = v;
        }
        // No trailing barrier: next iteration uses buffer set p^1; the
        // following reuse of set p is separated by that iteration's barrier.

        xa0 = na0; xb0 = nb0; xa1 = na1; xb1 = nb1;
        pi = npi;
        p ^= 1;
    }
}

extern "C" void kernel_launch(void* const* d_in, const int* in_sizes, int n_in,
                              void* d_out, int out_size)
{
    const float* X = (const float*)d_in[0];
    const void*  F = d_in[1];
    int rows = in_sizes[0] / TLEN;
    int npairs = rows / 2;

    int grid = 152;                 // GB300: 152 SMs, 1 CTA/SM persistent
    if (grid > npairs) grid = npairs;

    fused_kernel<<<grid, NTH>>>(
        X, (float*)d_out, rows,
        (const float*)d_in[2], (const float*)d_in[3], (const float*)d_in[4],
        (const float*)d_in[5], (const float*)d_in[6], (const float*)d_in[7], F);
}